// round 1
// baseline (speedup 1.0000x reference)
#include <cuda_runtime.h>
#include <cuda_bf16.h>
#include <cstdint>

#define N_NODES 50000
#define N_EDGES 600000
#define D_FEAT  128
#define OUT_DIM 128
#define K_DIM   256   // 2 * D_FEAT

// ---------------------------------------------------------------------------
// Scratch (static device globals; no allocation allowed in kernel_launch)
// ---------------------------------------------------------------------------
__device__ float4 g_sum4[N_NODES * (D_FEAT / 4)];  // segment sums, 25.6 MB
__device__ float  g_cnt [N_NODES];                 // segment counts

// ---------------------------------------------------------------------------
// Kernel 1: zero the scratch (must run every launch — graph replays)
// ---------------------------------------------------------------------------
__global__ void zero_scratch_kernel() {
    const int stride = gridDim.x * blockDim.x;
    int i = blockIdx.x * blockDim.x + threadIdx.x;
    const float4 z = make_float4(0.f, 0.f, 0.f, 0.f);
    for (int j = i; j < N_NODES * (D_FEAT / 4); j += stride) g_sum4[j] = z;
    for (int j = i; j < N_NODES; j += stride) g_cnt[j] = 0.f;
}

// ---------------------------------------------------------------------------
// Kernel 2: scatter-add. One warp per edge; each lane handles a float4 chunk.
// Vector reduction (red.global.add.v4.f32) -> 1 L2 atomic op per 16 bytes.
// ---------------------------------------------------------------------------
__global__ void scatter_kernel(const float* __restrict__ nbr_feat,
                               const int*   __restrict__ src_idx) {
    const int warp = (blockIdx.x * blockDim.x + threadIdx.x) >> 5;
    const int lane = threadIdx.x & 31;
    if (warp >= N_EDGES) return;

    const int dst = src_idx[warp];  // broadcast load (all lanes same addr)

    const float4 v = reinterpret_cast<const float4*>(nbr_feat)[warp * (D_FEAT / 4) + lane];

    float* p = reinterpret_cast<float*>(&g_sum4[dst * (D_FEAT / 4) + lane]);
    asm volatile("red.global.add.v4.f32 [%0], {%1, %2, %3, %4};"
                 :: "l"(p), "f"(v.x), "f"(v.y), "f"(v.z), "f"(v.w)
                 : "memory");

    if (lane == 0) atomicAdd(&g_cnt[dst], 1.0f);
}

// ---------------------------------------------------------------------------
// Kernel 3: fused mean-normalize + concat + GEMM.
//   out[n, j] = sum_k x[n,k] * W[k,j],  x = [self_feat[n,:], sum[n,:]/max(cnt,1)]
// W (256x128 fp32 = 128 KB) fully resident in smem.
// Block: 256 threads, BM=64 rows. Thread (t): cols j0=(t%32)*4, rows r0=(t/32)*8.
// Each thread: 8 rows x 4 cols fp32 accumulators -> inner loop is 32 indep FFMA
// + 1 LDS.128 (W) + 8 scalar LDS (x, warp-broadcast) per k.
// ---------------------------------------------------------------------------
#define BM   64
#define TPB  256
#define GEMM_SMEM ((K_DIM * OUT_DIM + BM * K_DIM) * 4)  // 131072 + 65536 = 196608 B

__global__ __launch_bounds__(TPB, 1)
void gemm_kernel(const float* __restrict__ self_feat,
                 const float* __restrict__ W,
                 float*       __restrict__ out) {
    extern __shared__ float sh[];
    float* Wsh = sh;                    // [K_DIM][OUT_DIM]
    float* Xsh = sh + K_DIM * OUT_DIM;  // [BM][K_DIM]

    const int tid = threadIdx.x;
    const int n0  = blockIdx.x * BM;

    // Load W into smem (8192 float4 / 256 threads = 32 each)
    {
        const float4* W4   = reinterpret_cast<const float4*>(W);
        float4*       Wsh4 = reinterpret_cast<float4*>(Wsh);
        #pragma unroll
        for (int i = tid; i < K_DIM * OUT_DIM / 4; i += TPB) Wsh4[i] = W4[i];
    }

    // Load x tile: first half = self_feat, second half = g_sum / max(cnt,1) (0 if cnt==0)
    {
        const float4* sf4 = reinterpret_cast<const float4*>(self_feat);
        const float4  z   = make_float4(0.f, 0.f, 0.f, 0.f);
        #pragma unroll
        for (int i = tid; i < BM * (D_FEAT / 4); i += TPB) {
            const int r  = i / (D_FEAT / 4);
            const int c4 = i % (D_FEAT / 4);
            const int n  = n0 + r;

            float4 vs = z, va = z;
            if (n < N_NODES) {
                vs = sf4[n * (D_FEAT / 4) + c4];
                const float c = g_cnt[n];
                const float s = (c > 0.f) ? (1.0f / c) : 0.0f;
                float4 t = g_sum4[n * (D_FEAT / 4) + c4];
                va = make_float4(t.x * s, t.y * s, t.z * s, t.w * s);
            }
            reinterpret_cast<float4*>(&Xsh[r * K_DIM])[c4]                = vs;
            reinterpret_cast<float4*>(&Xsh[r * K_DIM + D_FEAT])[c4]       = va;
        }
    }
    __syncthreads();

    const int j0 = (tid & 31) * 4;        // output column base (0..124)
    const int r0 = (tid >> 5) * 8;        // row base within tile (0..56)

    float acc[8][4];
    #pragma unroll
    for (int r = 0; r < 8; ++r)
        #pragma unroll
        for (int c = 0; c < 4; ++c) acc[r][c] = 0.f;

    #pragma unroll 4
    for (int k = 0; k < K_DIM; ++k) {
        const float4 w = *reinterpret_cast<const float4*>(&Wsh[k * OUT_DIM + j0]);
        #pragma unroll
        for (int r = 0; r < 8; ++r) {
            const float xv = Xsh[(r0 + r) * K_DIM + k];
            acc[r][0] += xv * w.x;
            acc[r][1] += xv * w.y;
            acc[r][2] += xv * w.z;
            acc[r][3] += xv * w.w;
        }
    }

    #pragma unroll
    for (int r = 0; r < 8; ++r) {
        const int n = n0 + r0 + r;
        if (n < N_NODES) {
            float4 v = make_float4(acc[r][0], acc[r][1], acc[r][2], acc[r][3]);
            *reinterpret_cast<float4*>(&out[n * OUT_DIM + j0]) = v;
        }
    }
}

// ---------------------------------------------------------------------------
// Launch
// ---------------------------------------------------------------------------
extern "C" void kernel_launch(void* const* d_in, const int* in_sizes, int n_in,
                              void* d_out, int out_size) {
    const float* self_feat = (const float*)d_in[0];   // [N_NODES, 128]
    const float* nbr_feat  = (const float*)d_in[1];   // [N_EDGES, 128]
    const int*   src_idx   = (const int*)  d_in[2];   // [N_EDGES]
    const float* W         = (const float*)d_in[3];   // [256, 128]
    float*       out       = (float*)d_out;           // [N_NODES, 128]

    (void)in_sizes; (void)n_in; (void)out_size;

    // 1) zero scratch
    zero_scratch_kernel<<<148 * 4, 256>>>();

    // 2) scatter (one warp per edge)
    {
        const int warps_per_block = 256 / 32;
        const int blocks = (N_EDGES + warps_per_block - 1) / warps_per_block;
        scatter_kernel<<<blocks, 256>>>(nbr_feat, src_idx);
    }

    // 3) fused mean + concat + GEMM
    {
        cudaFuncSetAttribute(gemm_kernel,
                             cudaFuncAttributeMaxDynamicSharedMemorySize,
                             GEMM_SMEM);
        const int blocks = (N_NODES + BM - 1) / BM;
        gemm_kernel<<<blocks, TPB, GEMM_SMEM>>>(self_feat, W, out);
    }
}

// round 2
// speedup vs baseline: 1.0659x; 1.0659x over previous
#include <cuda_runtime.h>
#include <cuda_bf16.h>
#include <cstdint>

#define N_NODES 50000
#define N_EDGES 600000
#define D_FEAT  128
#define OUT_DIM 128
#define K_DIM   256   // 2 * D_FEAT

// ---------------------------------------------------------------------------
// Scratch (static device globals; no allocation allowed in kernel_launch)
// ---------------------------------------------------------------------------
__device__ __align__(16) float g_sum[N_NODES * D_FEAT];  // segment sums, 25.6 MB
__device__ float g_cnt[N_NODES];                          // segment counts

// ---------------------------------------------------------------------------
// Kernel 1: zero the scratch (must run every launch — graph replays)
// ---------------------------------------------------------------------------
__global__ void zero_scratch_kernel() {
    const int stride = gridDim.x * blockDim.x;
    int i = blockIdx.x * blockDim.x + threadIdx.x;
    float4* s4 = reinterpret_cast<float4*>(g_sum);
    const float4 z = make_float4(0.f, 0.f, 0.f, 0.f);
    for (int j = i; j < N_NODES * (D_FEAT / 4); j += stride) s4[j] = z;
    for (int j = i; j < N_NODES; j += stride) g_cnt[j] = 0.f;
}

// ---------------------------------------------------------------------------
// Kernel 2: scatter-add via TMA bulk reduction.
// Previous version used red.global.add.v4.f32 (32 REDG per edge) and was
// REDG-issue-bound (~1.29 cyc/lane * 19.2M lane-ops ≈ 88us). Now: stage 64
// contiguous edge rows in smem, then ONE cp.reduce.async.bulk (512B) per edge.
// The add happens in the LTS; SM issue cost is ~1 instr per edge.
// ---------------------------------------------------------------------------
#define E_PER_BLK 64

__global__ __launch_bounds__(256)
void scatter_tma_kernel(const float* __restrict__ nbr_feat,
                        const int*   __restrict__ src_idx) {
    __shared__ __align__(16) float staged[E_PER_BLK * D_FEAT];  // 32 KB
    __shared__ int sidx[E_PER_BLK];

    const int tid = threadIdx.x;
    const size_t e0 = (size_t)blockIdx.x * E_PER_BLK;

    // Coalesced contiguous copy: rows e0..e0+63 are adjacent in nbr_feat.
    const float4* src4 = reinterpret_cast<const float4*>(nbr_feat) + e0 * (D_FEAT / 4);
    float4* st4 = reinterpret_cast<float4*>(staged);
    #pragma unroll 8
    for (int i = tid; i < E_PER_BLK * (D_FEAT / 4); i += 256)
        st4[i] = src4[i];

    if (tid < E_PER_BLK) sidx[tid] = src_idx[e0 + tid];

    // Make generic-proxy smem writes visible to the async proxy, then sync.
    asm volatile("fence.proxy.async.shared::cta;" ::: "memory");
    __syncthreads();

    if (tid < E_PER_BLK) {
        const int dst = sidx[tid];
        float* gdst = g_sum + (size_t)dst * D_FEAT;
        unsigned saddr = (unsigned)__cvta_generic_to_shared(&staged[tid * D_FEAT]);
        asm volatile(
            "cp.reduce.async.bulk.global.shared::cta.bulk_group.add.f32 [%0], [%1], %2;"
            :: "l"(gdst), "r"(saddr), "r"(D_FEAT * 4) : "memory");
        atomicAdd(&g_cnt[dst], 1.0f);
    }

    // All issued bulk ops must complete before smem is released at block exit.
    asm volatile("cp.async.bulk.commit_group;" ::: "memory");
    asm volatile("cp.async.bulk.wait_group 0;" ::: "memory");
}

// ---------------------------------------------------------------------------
// Kernel 3: fused mean-normalize + concat + GEMM, with packed fma.rn.f32x2
// (2 fp32 FMAs per fma-pipe issue slot, exact fp32 semantics).
// Block: 256 threads, BM=64 rows. Thread t: cols j0=(t%32)*4, rows r0=(t/32)*8.
// Inner loop steps k by 2: x loaded as float2 broadcast (one LDS.64 per row
// per 2 k's), W loaded as 8B pairs, 4 packed FMAs per row per 2 k's.
// ---------------------------------------------------------------------------
#define BM   64
#define TPB  256
#define GEMM_SMEM ((K_DIM * OUT_DIM + BM * K_DIM) * 4)  // 131072 + 65536 = 196608 B

__global__ __launch_bounds__(TPB, 1)
void gemm_kernel(const float* __restrict__ self_feat,
                 const float* __restrict__ W,
                 float*       __restrict__ out) {
    extern __shared__ float sh[];
    float* Wsh = sh;                    // [K_DIM][OUT_DIM]
    float* Xsh = sh + K_DIM * OUT_DIM;  // [BM][K_DIM]

    const int tid = threadIdx.x;
    const int n0  = blockIdx.x * BM;

    // Load W into smem (8192 float4 / 256 threads = 32 each)
    {
        const float4* W4   = reinterpret_cast<const float4*>(W);
        float4*       Wsh4 = reinterpret_cast<float4*>(Wsh);
        #pragma unroll
        for (int i = tid; i < K_DIM * OUT_DIM / 4; i += TPB) Wsh4[i] = W4[i];
    }

    // Load x tile: first half = self_feat, second half = g_sum / cnt (0 if cnt==0)
    {
        const float4* sf4 = reinterpret_cast<const float4*>(self_feat);
        const float4* gs4 = reinterpret_cast<const float4*>(g_sum);
        const float4  z   = make_float4(0.f, 0.f, 0.f, 0.f);
        #pragma unroll
        for (int i = tid; i < BM * (D_FEAT / 4); i += TPB) {
            const int r  = i / (D_FEAT / 4);
            const int c4 = i % (D_FEAT / 4);
            const int n  = n0 + r;

            float4 vs = z, va = z;
            if (n < N_NODES) {
                vs = sf4[n * (D_FEAT / 4) + c4];
                const float c = g_cnt[n];
                const float s = (c > 0.f) ? (1.0f / c) : 0.0f;
                float4 t = gs4[n * (D_FEAT / 4) + c4];
                va = make_float4(t.x * s, t.y * s, t.z * s, t.w * s);
            }
            reinterpret_cast<float4*>(&Xsh[r * K_DIM])[c4]          = vs;
            reinterpret_cast<float4*>(&Xsh[r * K_DIM + D_FEAT])[c4] = va;
        }
    }
    __syncthreads();

    const int j0 = (tid & 31) * 4;   // output column base (0..124)
    const int r0 = (tid >> 5) * 8;   // row base within tile (0..56)

    unsigned long long a01[8], a23[8];
    #pragma unroll
    for (int r = 0; r < 8; ++r) { a01[r] = 0ull; a23[r] = 0ull; }

    #pragma unroll 2
    for (int k = 0; k < K_DIM; k += 2) {
        const unsigned long long wA0 =
            *reinterpret_cast<const unsigned long long*>(&Wsh[k * OUT_DIM + j0]);
        const unsigned long long wB0 =
            *reinterpret_cast<const unsigned long long*>(&Wsh[k * OUT_DIM + j0 + 2]);
        const unsigned long long wA1 =
            *reinterpret_cast<const unsigned long long*>(&Wsh[(k + 1) * OUT_DIM + j0]);
        const unsigned long long wB1 =
            *reinterpret_cast<const unsigned long long*>(&Wsh[(k + 1) * OUT_DIM + j0 + 2]);

        #pragma unroll
        for (int r = 0; r < 8; ++r) {
            const float2 x = *reinterpret_cast<const float2*>(&Xsh[(r0 + r) * K_DIM + k]);
            unsigned long long xx0, xx1;
            asm("mov.b64 %0, {%1, %1};" : "=l"(xx0) : "f"(x.x));
            asm("mov.b64 %0, {%1, %1};" : "=l"(xx1) : "f"(x.y));
            asm("fma.rn.f32x2 %0, %1, %2, %0;" : "+l"(a01[r]) : "l"(xx0), "l"(wA0));
            asm("fma.rn.f32x2 %0, %1, %2, %0;" : "+l"(a23[r]) : "l"(xx0), "l"(wB0));
            asm("fma.rn.f32x2 %0, %1, %2, %0;" : "+l"(a01[r]) : "l"(xx1), "l"(wA1));
            asm("fma.rn.f32x2 %0, %1, %2, %0;" : "+l"(a23[r]) : "l"(xx1), "l"(wB1));
        }
    }

    #pragma unroll
    for (int r = 0; r < 8; ++r) {
        const int n = n0 + r0 + r;
        if (n < N_NODES) {
            float o0, o1, o2, o3;
            asm("mov.b64 {%0, %1}, %2;" : "=f"(o0), "=f"(o1) : "l"(a01[r]));
            asm("mov.b64 {%0, %1}, %2;" : "=f"(o2), "=f"(o3) : "l"(a23[r]));
            *reinterpret_cast<float4*>(&out[(size_t)n * OUT_DIM + j0]) =
                make_float4(o0, o1, o2, o3);
        }
    }
}

// ---------------------------------------------------------------------------
// Launch
// ---------------------------------------------------------------------------
extern "C" void kernel_launch(void* const* d_in, const int* in_sizes, int n_in,
                              void* d_out, int out_size) {
    const float* self_feat = (const float*)d_in[0];   // [N_NODES, 128]
    const float* nbr_feat  = (const float*)d_in[1];   // [N_EDGES, 128]
    const int*   src_idx   = (const int*)  d_in[2];   // [N_EDGES]
    const float* W         = (const float*)d_in[3];   // [256, 128]
    float*       out       = (float*)d_out;           // [N_NODES, 128]

    (void)in_sizes; (void)n_in; (void)out_size;

    // 1) zero scratch
    zero_scratch_kernel<<<148 * 8, 256>>>();

    // 2) scatter via TMA bulk reduce (64 edges per block; 600000/64 = 9375 exact)
    scatter_tma_kernel<<<N_EDGES / E_PER_BLK, 256>>>(nbr_feat, src_idx);

    // 3) fused mean + concat + GEMM (f32x2 packed)
    {
        cudaFuncSetAttribute(gemm_kernel,
                             cudaFuncAttributeMaxDynamicSharedMemorySize,
                             GEMM_SMEM);
        const int blocks = (N_NODES + BM - 1) / BM;
        gemm_kernel<<<blocks, TPB, GEMM_SMEM>>>(self_feat, W, out);
    }
}

// round 3
// speedup vs baseline: 1.0946x; 1.0269x over previous
#include <cuda_runtime.h>
#include <cuda_bf16.h>
#include <cstdint>

#define N_NODES 50000
#define N_EDGES 600000
#define D_FEAT  128
#define OUT_DIM 128
#define K_DIM   256   // 2 * D_FEAT

#define SCAN_BLK 512
#define N_SCAN_BLKS ((N_NODES + SCAN_BLK - 1) / SCAN_BLK)   // 98

// ---------------------------------------------------------------------------
// Scratch (static device globals; no allocation allowed anywhere)
// ---------------------------------------------------------------------------
__device__ int g_cnt_i [N_NODES];    // edge count per node
__device__ int g_cursor[N_NODES];    // scatter cursors
__device__ int g_off   [N_NODES];    // exclusive prefix (segment start)
__device__ int g_btot  [N_SCAN_BLKS];
__device__ int g_boff  [N_SCAN_BLKS];
__device__ int g_eid   [N_EDGES];    // edge ids sorted by destination node
__device__ __align__(16) float g_agg[N_NODES * D_FEAT];  // normalized means (25.6 MB)

// ---------------------------------------------------------------------------
// Kernel 0: zero the counters (only 400 KB now — g_agg is overwritten, not
// accumulated, so it needs no clearing)
// ---------------------------------------------------------------------------
__global__ void zero_counters_kernel() {
    int i = blockIdx.x * blockDim.x + threadIdx.x;
    if (i < N_NODES) { g_cnt_i[i] = 0; g_cursor[i] = 0; }
}

// ---------------------------------------------------------------------------
// Kernel 1: histogram of destination nodes
// ---------------------------------------------------------------------------
__global__ void count_kernel(const int* __restrict__ src_idx) {
    int e = blockIdx.x * blockDim.x + threadIdx.x;
    if (e < N_EDGES) atomicAdd(&g_cnt_i[src_idx[e]], 1);
}

// ---------------------------------------------------------------------------
// Kernel 2a: per-block exclusive scan (Hillis-Steele over 512 elems)
// ---------------------------------------------------------------------------
__global__ __launch_bounds__(SCAN_BLK)
void scan_partial_kernel() {
    __shared__ int sh[SCAN_BLK];
    const int tid = threadIdx.x;
    const int i   = blockIdx.x * SCAN_BLK + tid;
    const int v   = (i < N_NODES) ? g_cnt_i[i] : 0;
    sh[tid] = v;
    __syncthreads();
    #pragma unroll
    for (int d = 1; d < SCAN_BLK; d <<= 1) {
        int t = (tid >= d) ? sh[tid - d] : 0;
        __syncthreads();
        sh[tid] += t;
        __syncthreads();
    }
    if (i < N_NODES) g_off[i] = sh[tid] - v;          // exclusive within block
    if (tid == SCAN_BLK - 1) g_btot[blockIdx.x] = sh[tid];
}

// Kernel 2b: scan the 98 block totals (trivial size -> single thread)
__global__ void scan_btot_kernel() {
    int run = 0;
    for (int b = 0; b < N_SCAN_BLKS; ++b) { g_boff[b] = run; run += g_btot[b]; }
}

// Kernel 2c: fold block offsets back in
__global__ void add_boff_kernel() {
    int i = blockIdx.x * blockDim.x + threadIdx.x;
    if (i < N_NODES) g_off[i] += g_boff[i / SCAN_BLK];
}

// ---------------------------------------------------------------------------
// Kernel 3: scatter edge ids into destination-sorted order
// ---------------------------------------------------------------------------
__global__ void scatter_ids_kernel(const int* __restrict__ src_idx) {
    int e = blockIdx.x * blockDim.x + threadIdx.x;
    if (e < N_EDGES) {
        const int s = src_idx[e];
        const int pos = g_off[s] + atomicAdd(&g_cursor[s], 1);
        g_eid[pos] = e;
    }
}

// ---------------------------------------------------------------------------
// Kernel 4: gather-reduce. One warp per node; lane l owns columns [4l, 4l+4).
// Pure coalesced 512B-row streaming — no atomics on feature data at all.
// Fuses the mean normalization; writes g_agg.
// ---------------------------------------------------------------------------
__global__ __launch_bounds__(256)
void gather_kernel(const float* __restrict__ nbr_feat) {
    const int warp = (blockIdx.x * blockDim.x + threadIdx.x) >> 5;
    const int lane = threadIdx.x & 31;
    if (warp >= N_NODES) return;

    const int base = g_off[warp];
    const int deg  = g_cnt_i[warp];

    const float4* nb4 = reinterpret_cast<const float4*>(nbr_feat);
    float4 acc = make_float4(0.f, 0.f, 0.f, 0.f);

    int i = 0;
    for (; i + 2 <= deg; i += 2) {                  // unroll-by-2 for MLP
        const int e0 = g_eid[base + i];
        const int e1 = g_eid[base + i + 1];
        const float4 v0 = nb4[(size_t)e0 * (D_FEAT / 4) + lane];
        const float4 v1 = nb4[(size_t)e1 * (D_FEAT / 4) + lane];
        acc.x += v0.x + v1.x;  acc.y += v0.y + v1.y;
        acc.z += v0.z + v1.z;  acc.w += v0.w + v1.w;
    }
    if (i < deg) {
        const int e = g_eid[base + i];
        const float4 v = nb4[(size_t)e * (D_FEAT / 4) + lane];
        acc.x += v.x; acc.y += v.y; acc.z += v.z; acc.w += v.w;
    }

    const float s = (deg > 0) ? (1.0f / (float)deg) : 0.0f;
    acc.x *= s; acc.y *= s; acc.z *= s; acc.w *= s;
    reinterpret_cast<float4*>(g_agg)[(size_t)warp * (D_FEAT / 4) + lane] = acc;
}

// ---------------------------------------------------------------------------
// Kernel 5: fused concat + GEMM with packed fma.rn.f32x2 (exact fp32 pairs).
// Block: 256 threads, BM=64 rows. Thread t: cols j0=(t%32)*4, rows r0=(t/32)*8.
// ---------------------------------------------------------------------------
#define BM   64
#define TPB  256
#define GEMM_SMEM ((K_DIM * OUT_DIM + BM * K_DIM) * 4)  // 196608 B

__global__ __launch_bounds__(TPB, 1)
void gemm_kernel(const float* __restrict__ self_feat,
                 const float* __restrict__ W,
                 float*       __restrict__ out) {
    extern __shared__ float sh[];
    float* Wsh = sh;                    // [K_DIM][OUT_DIM]
    float* Xsh = sh + K_DIM * OUT_DIM;  // [BM][K_DIM]

    const int tid = threadIdx.x;
    const int n0  = blockIdx.x * BM;

    // Load W into smem
    {
        const float4* W4   = reinterpret_cast<const float4*>(W);
        float4*       Wsh4 = reinterpret_cast<float4*>(Wsh);
        #pragma unroll
        for (int i = tid; i < K_DIM * OUT_DIM / 4; i += TPB) Wsh4[i] = W4[i];
    }

    // Load x tile: [self_feat | g_agg] (g_agg already normalized)
    {
        const float4* sf4 = reinterpret_cast<const float4*>(self_feat);
        const float4* ag4 = reinterpret_cast<const float4*>(g_agg);
        const float4  z   = make_float4(0.f, 0.f, 0.f, 0.f);
        #pragma unroll
        for (int i = tid; i < BM * (D_FEAT / 4); i += TPB) {
            const int r  = i / (D_FEAT / 4);
            const int c4 = i % (D_FEAT / 4);
            const int n  = n0 + r;
            float4 vs = z, va = z;
            if (n < N_NODES) {
                vs = sf4[(size_t)n * (D_FEAT / 4) + c4];
                va = ag4[(size_t)n * (D_FEAT / 4) + c4];
            }
            reinterpret_cast<float4*>(&Xsh[r * K_DIM])[c4]          = vs;
            reinterpret_cast<float4*>(&Xsh[r * K_DIM + D_FEAT])[c4] = va;
        }
    }
    __syncthreads();

    const int j0 = (tid & 31) * 4;   // output column base
    const int r0 = (tid >> 5) * 8;   // row base within tile

    unsigned long long a01[8], a23[8];
    #pragma unroll
    for (int r = 0; r < 8; ++r) { a01[r] = 0ull; a23[r] = 0ull; }

    #pragma unroll 2
    for (int k = 0; k < K_DIM; k += 2) {
        const unsigned long long wA0 =
            *reinterpret_cast<const unsigned long long*>(&Wsh[k * OUT_DIM + j0]);
        const unsigned long long wB0 =
            *reinterpret_cast<const unsigned long long*>(&Wsh[k * OUT_DIM + j0 + 2]);
        const unsigned long long wA1 =
            *reinterpret_cast<const unsigned long long*>(&Wsh[(k + 1) * OUT_DIM + j0]);
        const unsigned long long wB1 =
            *reinterpret_cast<const unsigned long long*>(&Wsh[(k + 1) * OUT_DIM + j0 + 2]);

        #pragma unroll
        for (int r = 0; r < 8; ++r) {
            const float2 x = *reinterpret_cast<const float2*>(&Xsh[(r0 + r) * K_DIM + k]);
            unsigned long long xx0, xx1;
            asm("mov.b64 %0, {%1, %1};" : "=l"(xx0) : "f"(x.x));
            asm("mov.b64 %0, {%1, %1};" : "=l"(xx1) : "f"(x.y));
            asm("fma.rn.f32x2 %0, %1, %2, %0;" : "+l"(a01[r]) : "l"(xx0), "l"(wA0));
            asm("fma.rn.f32x2 %0, %1, %2, %0;" : "+l"(a23[r]) : "l"(xx0), "l"(wB0));
            asm("fma.rn.f32x2 %0, %1, %2, %0;" : "+l"(a01[r]) : "l"(xx1), "l"(wA1));
            asm("fma.rn.f32x2 %0, %1, %2, %0;" : "+l"(a23[r]) : "l"(xx1), "l"(wB1));
        }
    }

    #pragma unroll
    for (int r = 0; r < 8; ++r) {
        const int n = n0 + r0 + r;
        if (n < N_NODES) {
            float o0, o1, o2, o3;
            asm("mov.b64 {%0, %1}, %2;" : "=f"(o0), "=f"(o1) : "l"(a01[r]));
            asm("mov.b64 {%0, %1}, %2;" : "=f"(o2), "=f"(o3) : "l"(a23[r]));
            *reinterpret_cast<float4*>(&out[(size_t)n * OUT_DIM + j0]) =
                make_float4(o0, o1, o2, o3);
        }
    }
}

// ---------------------------------------------------------------------------
// Launch
// ---------------------------------------------------------------------------
extern "C" void kernel_launch(void* const* d_in, const int* in_sizes, int n_in,
                              void* d_out, int out_size) {
    const float* self_feat = (const float*)d_in[0];   // [N_NODES, 128]
    const float* nbr_feat  = (const float*)d_in[1];   // [N_EDGES, 128]
    const int*   src_idx   = (const int*)  d_in[2];   // [N_EDGES]
    const float* W         = (const float*)d_in[3];   // [256, 128]
    float*       out       = (float*)d_out;           // [N_NODES, 128]

    (void)in_sizes; (void)n_in; (void)out_size;

    const int nodes_blks = (N_NODES + 255) / 256;
    const int edges_blks = (N_EDGES + 255) / 256;

    // Sort pipeline (all tiny-int work)
    zero_counters_kernel<<<nodes_blks, 256>>>();
    count_kernel<<<edges_blks, 256>>>(src_idx);
    scan_partial_kernel<<<N_SCAN_BLKS, SCAN_BLK>>>();
    scan_btot_kernel<<<1, 1>>>();
    add_boff_kernel<<<nodes_blks, 256>>>();
    scatter_ids_kernel<<<edges_blks, 256>>>(src_idx);

    // Gather-reduce (one warp per node; 8 warps per block)
    gather_kernel<<<(N_NODES + 7) / 8, 256>>>(nbr_feat);

    // Fused concat + GEMM
    {
        cudaFuncSetAttribute(gemm_kernel,
                             cudaFuncAttributeMaxDynamicSharedMemorySize,
                             GEMM_SMEM);
        gemm_kernel<<<(N_NODES + BM - 1) / BM, TPB, GEMM_SMEM>>>(self_feat, W, out);
    }
}